// round 16
// baseline (speedup 1.0000x reference)
#include <cuda_runtime.h>
#include <cuda_fp16.h>
#include <mma.h>
#include <math.h>
#include <stdint.h>

using namespace nvcuda;

// ---------------- problem constants ----------------
#define N_NODES 10000
#define N_EDGES 80000
#define N_GRAPHS 64
#define HEADS 8
#define F_IN 128
#define D1 512
#define D2 256
#define D3 128
#define OUT_DIM 10

#define ZCOLS (HEADS * F_IN)          // 1024
#define MCOLS (ZCOLS + 128)           // 1152

#define F_N1 (MCOLS + HEADS * D1 + D1)   // 5760
#define F_N2 (3 * HEADS * D2 + D2)       // 6400
#define F_N3 (3 * HEADS * D3 + D3)       // 3200
#define WF_BASE1 0LL
#define WF_BASE2 ((long long)F_IN * F_N1)
#define WF_BASE3 (WF_BASE2 + (long long)D1 * F_N2)
#define WF_TOTAL (WF_BASE3 + (long long)D2 * F_N3)

#define BB1 0
#define BB2 F_N1
#define BB3 (BB2 + F_N2)
#define BTOTAL (BB3 + F_N3)
#define NXTOT (N_NODES * F_IN)
#define QKTOT (2 * F_IN * HEADS * D1)    // 1048576
#define POOLINIT (N_GRAPHS + N_GRAPHS + N_GRAPHS * D3)  // gmax + gsum + pool

// ---------------- device scratch (static, no allocs) ----------------
__device__ float g_q[(size_t)N_NODES * (HEADS * D1)];
__device__ __half g_k[(size_t)N_NODES * (HEADS * D1)];
__device__ __half g_v[(size_t)N_NODES * (HEADS * D1)];
__device__ float g_skip[(size_t)N_NODES * D1];
__device__ float g_hA[(size_t)N_NODES * D1];

__device__ float g_extras[(size_t)N_NODES * 128];
__device__ __half g_x16[(size_t)N_NODES * F_IN];
__device__ __half g_Af16[(size_t)N_NODES * D1];

__device__ __half g_A16[8 * 128 * 512];
__device__ __half g_BT16[8 * 512 * 128];

__device__ __half g_WF[WF_TOTAL];
__device__ float g_bias[BTOTAL];

__device__ int g_deg[N_NODES];
__device__ int g_ptr[N_NODES + 1];
__device__ int g_fill[N_NODES];
__device__ int g_csr_src[N_EDGES];

__device__ float g_gate[N_NODES];
__device__ float g_gmax[N_GRAPHS];
__device__ float g_gsum[N_GRAPHS];
__device__ float g_pool[N_GRAPHS * D3];

// ---------------- cp.async helpers ----------------
__device__ __forceinline__ void cp16(uint32_t dst, const void* src)
{
    asm volatile("cp.async.cg.shared.global [%0], [%1], 16;" :: "r"(dst), "l"(src));
}
__device__ __forceinline__ void cp_commit() { asm volatile("cp.async.commit_group;"); }
template <int Np>
__device__ __forceinline__ void cp_wait() { asm volatile("cp.async.wait_group %0;" :: "n"(Np)); }

// ---------------- one-shot packing ----------------
struct PackArgs {
    const float* wsrc[12];
    long long wcum[13];
    int wncols[12];
    long long wdstBase[12];
    int wntot[12];
    int wcoff[12];
    const float* bsrc[12];
    int bcum[13];
    int boff[12];
    const float* x;
    const float* wq;
    const float* wk;
    const int* ei;
};

__global__ void pack_all(PackArgs P, __half* __restrict__ WF, __half* __restrict__ x16,
                         float* __restrict__ bias, __half* __restrict__ A16,
                         __half* __restrict__ BT16, int* __restrict__ deg,
                         float* __restrict__ gmax, float* __restrict__ gsum,
                         float* __restrict__ pool,
                         long long wtotal, long long xtotal, int btotal)
{
    long long i = (long long)blockIdx.x * blockDim.x + threadIdx.x;
    if (i < wtotal) {
        int r = 0;
        while (i >= P.wcum[r + 1]) r++;
        const long long li = i - P.wcum[r];
        const int nc = P.wncols[r];
        const int k = (int)(li / nc), c = (int)(li % nc);
        const long long di = P.wdstBase[r] + (long long)k * P.wntot[r] + P.wcoff[r] + c;
        WF[di] = __float2half(P.wsrc[r][li]);
        return;
    }
    i -= wtotal;
    if (i < xtotal) {
        x16[i] = __float2half(P.x[i]);
        return;
    }
    i -= xtotal;
    if (i < btotal) {
        int j = (int)i;
        int r = 0;
        while (j >= P.bcum[r + 1]) r++;
        bias[P.boff[r] + (j - P.bcum[r])] = P.bsrc[r][j - P.bcum[r]];
        return;
    }
    i -= btotal;
    if (i < QKTOT) {
        if (i < QKTOT / 2) {
            const int idx = (int)i;
            const int k = idx >> 12, c = idx & 4095;
            const int h = c >> 9, cc = c & 511;
            A16[(size_t)h * 65536 + k * 512 + cc] = __float2half(P.wq[idx]);
        } else {
            const int idx = (int)(i - QKTOT / 2);
            const int j = idx >> 12, c = idx & 4095;
            const int h = c >> 9, cc = c & 511;
            BT16[(size_t)h * 65536 + cc * 128 + j] = __float2half(P.wk[idx]);
        }
        return;
    }
    i -= QKTOT;
    if (i < N_EDGES) {
        atomicAdd(&deg[P.ei[N_EDGES + (int)i]], 1);
        return;
    }
    i -= N_EDGES;
    if (i < POOLINIT) {
        const int j = (int)i;
        if (j < N_GRAPHS) gmax[j] = -INFINITY;
        else if (j < 2 * N_GRAPHS) gsum[j - N_GRAPHS] = 0.f;
        else pool[j - 2 * N_GRAPHS] = 0.f;
    }
}

// ---------------- batched per-head MM: M_h = Wq_h @ Wk_h^T ----------------
#define LDAH 40
#define LDBH 136
#define ASZH (128 * LDAH)
#define BSZH (32 * LDBH)
#define STAGE_H (ASZH + BSZH)

__global__ __launch_bounds__(256, 2)
void make_m_mm(const __half* __restrict__ A16, const __half* __restrict__ BT16,
               __half* __restrict__ WF)
{
    __shared__ __align__(16) __half sm[2 * STAGE_H];

    const int tid = threadIdx.x;
    const int warpId = tid >> 5;
    const int lane = tid & 31;
    const int wm = warpId >> 2;
    const int wn = warpId & 3;
    const int h = blockIdx.y;
    const __half* A = A16 + (size_t)h * 128 * 512;
    const __half* B = BT16 + (size_t)h * 512 * 128;
    constexpr int K = 512, N = 128;

    const int ar = tid >> 1, ac = (tid & 1) * 16;
    const int br = tid >> 3, bc = (tid & 7) * 16;

    wmma::fragment<wmma::accumulator, 16, 16, 16, float> acc[4][2];
#pragma unroll
    for (int i = 0; i < 4; i++)
#pragma unroll
        for (int j = 0; j < 2; j++) wmma::fill_fragment(acc[i][j], 0.f);

    auto issue = [&](int kb, int s) {
        __half* base = sm + s * STAGE_H;
        __half* pA = base + ar * LDAH + ac;
        const size_t off = (size_t)ar * K + kb + ac;
        cp16((uint32_t)__cvta_generic_to_shared(pA),     A + off);
        cp16((uint32_t)__cvta_generic_to_shared(pA + 8), A + off + 8);
        __half* pB = base + ASZH + br * LDBH + bc;
        const size_t boff = (size_t)(kb + br) * N + bc;
        cp16((uint32_t)__cvta_generic_to_shared(pB),     B + boff);
        cp16((uint32_t)__cvta_generic_to_shared(pB + 8), B + boff + 8);
        cp_commit();
    };

    const int nk = K >> 5;
    issue(0, 0);

    for (int it = 0; it < nk; ++it) {
        const int s = it & 1;
        if (it + 1 < nk) { issue((it + 1) << 5, s ^ 1); cp_wait<1>(); }
        else             { cp_wait<0>(); }
        __syncthreads();

        const __half* As = sm + s * STAGE_H;
        const __half* Bs = As + ASZH;

#pragma unroll
        for (int kk = 0; kk < 2; kk++) {
            wmma::fragment<wmma::matrix_a, 16, 16, 16, __half, wmma::row_major> af[4];
            wmma::fragment<wmma::matrix_b, 16, 16, 16, __half, wmma::row_major> bf[2];
#pragma unroll
            for (int i = 0; i < 4; i++)
                wmma::load_matrix_sync(af[i], As + (wm * 64 + i * 16) * LDAH + kk * 16, LDAH);
#pragma unroll
            for (int j = 0; j < 2; j++)
                wmma::load_matrix_sync(bf[j], Bs + (kk * 16) * LDBH + wn * 32 + j * 16, LDBH);
#pragma unroll
            for (int i = 0; i < 4; i++)
#pragma unroll
                for (int j = 0; j < 2; j++)
                    wmma::mma_sync(acc[i][j], af[i], bf[j], acc[i][j]);
        }
        __syncthreads();
    }

    float* wb = reinterpret_cast<float*>(sm) + warpId * 256;
#pragma unroll
    for (int i = 0; i < 4; i++)
#pragma unroll
        for (int j = 0; j < 2; j++) {
            wmma::store_matrix_sync(wb, acc[i][j], 16, wmma::mem_row_major);
            __syncwarp();
            const int r0 = wm * 64 + i * 16;
            const int c0 = wn * 32 + j * 16;
#pragma unroll
            for (int e = lane; e < 64; e += 32) {
                const int rr = e >> 2, c4 = (e & 3) * 4;
                const float4 vv = *reinterpret_cast<float4*>(wb + rr * 16 + c4);
                uint2 p;
                *reinterpret_cast<__half2*>(&p.x) = __floats2half2_rn(vv.x, vv.y);
                *reinterpret_cast<__half2*>(&p.y) = __floats2half2_rn(vv.z, vv.w);
                *reinterpret_cast<uint2*>(&WF[WF_BASE1 + (size_t)(r0 + rr) * F_N1
                                              + h * 128 + c0 + c4]) = p;
            }
            __syncwarp();
        }
}

// ---------------- extras columns + L1 logit bias ----------------
__global__ void m_extras(const float* __restrict__ wq, const float* __restrict__ wk,
                         const float* __restrict__ bq, const float* __restrict__ bk,
                         __half* __restrict__ WF, float* __restrict__ bias)
{
    __shared__ float red[128];
    const int j = blockIdx.x;
    const int tid = threadIdx.x;

    if (j < ZCOLS) {
        if (tid == 0) bias[j] = 0.f;
        return;
    }
    if (j >= 1040) {
        WF[WF_BASE1 + (size_t)tid * F_N1 + j] = __float2half(0.f);
        if (tid == 0) bias[j] = 0.f;
        return;
    }

    const bool isAlpha = (j < 1032);
    const int h = isAlpha ? (j - 1024) : (j - 1032);
    const int base = h * D1;
    const float* mat = isAlpha ? wq : wk;
    const float* vec = isAlpha ? bk : bq;

    const float4* row4 = reinterpret_cast<const float4*>(mat + (size_t)tid * (HEADS * D1) + base);
    const float4* vec4 = reinterpret_cast<const float4*>(vec + base);
    float acc = 0.f;
#pragma unroll 4
    for (int c = 0; c < D1 / 4; c++) {
        const float4 r = row4[c];
        const float4 v = vec4[c];
        acc += r.x * v.x + r.y * v.y + r.z * v.z + r.w * v.w;
    }
    WF[WF_BASE1 + (size_t)tid * F_N1 + j] = __float2half(acc);

    if (isAlpha) {
        float p = 0.f;
        for (int c = tid; c < D1; c += 128) p += bq[base + c] * bk[base + c];
        red[tid] = p;
        __syncthreads();
        if (tid < 64) red[tid] += red[tid + 64];
        __syncthreads();
        if (tid < 32) {
            float t = red[tid] + red[tid + 32];
#pragma unroll
            for (int o = 16; o > 0; o >>= 1) t += __shfl_down_sync(0xffffffffu, t, o);
            if (tid == 0) bias[j] = t;
        }
    } else {
        if (tid == 0) bias[j] = 0.f;
    }
}

// ---------------- epilogue routing table ----------------
struct EpiTab {
    float* f[4];
    __half* h[4];
    int stride[4];
    int start[4];
};

// ---------------- fp16 single-pass GEMM, BK=32 ----------------
__global__ __launch_bounds__(256, 2)
void gemm_half(const __half* __restrict__ A, const __half* __restrict__ B,
               const float* __restrict__ bias, EpiTab T,
               int M, int N, int K)
{
    __shared__ __align__(16) __half sm[2 * STAGE_H];

    const int tid = threadIdx.x;
    const int warpId = tid >> 5;
    const int lane = tid & 31;
    const int wm = warpId >> 2;
    const int wn = warpId & 3;
    const int bm = blockIdx.y * 128;
    const int bn = blockIdx.x * 128;

    const int ar = tid >> 1, ac = (tid & 1) * 16;
    const int br = tid >> 3, bc = (tid & 7) * 16;

    wmma::fragment<wmma::accumulator, 16, 16, 16, float> acc[4][2];
#pragma unroll
    for (int i = 0; i < 4; i++)
#pragma unroll
        for (int j = 0; j < 2; j++) wmma::fill_fragment(acc[i][j], 0.f);

    auto issue = [&](int kb, int s) {
        __half* base = sm + s * STAGE_H;
        __half* pA = base + ar * LDAH + ac;
        const int gr = bm + ar;
        if (gr < M) {
            const size_t off = (size_t)gr * K + kb + ac;
            cp16((uint32_t)__cvta_generic_to_shared(pA),     A + off);
            cp16((uint32_t)__cvta_generic_to_shared(pA + 8), A + off + 8);
        } else {
            uint4 z = make_uint4(0, 0, 0, 0);
            *reinterpret_cast<uint4*>(pA) = z;
            *reinterpret_cast<uint4*>(pA + 8) = z;
        }
        __half* pB = base + ASZH + br * LDBH + bc;
        const size_t boff = (size_t)(kb + br) * N + bn + bc;
        cp16((uint32_t)__cvta_generic_to_shared(pB),     B + boff);
        cp16((uint32_t)__cvta_generic_to_shared(pB + 8), B + boff + 8);
        cp_commit();
    };

    const int nk = K >> 5;
    issue(0, 0);

    for (int it = 0; it < nk; ++it) {
        const int s = it & 1;
        if (it + 1 < nk) { issue((it + 1) << 5, s ^ 1); cp_wait<1>(); }
        else             { cp_wait<0>(); }
        __syncthreads();

        const __half* As = sm + s * STAGE_H;
        const __half* Bs = As + ASZH;

#pragma unroll
        for (int kk = 0; kk < 2; kk++) {
            wmma::fragment<wmma::matrix_a, 16, 16, 16, __half, wmma::row_major> af[4];
            wmma::fragment<wmma::matrix_b, 16, 16, 16, __half, wmma::row_major> bf[2];
#pragma unroll
            for (int i = 0; i < 4; i++)
                wmma::load_matrix_sync(af[i], As + (wm * 64 + i * 16) * LDAH + kk * 16, LDAH);
#pragma unroll
            for (int j = 0; j < 2; j++)
                wmma::load_matrix_sync(bf[j], Bs + (kk * 16) * LDBH + wn * 32 + j * 16, LDBH);
#pragma unroll
            for (int i = 0; i < 4; i++)
#pragma unroll
                for (int j = 0; j < 2; j++)
                    wmma::mma_sync(acc[i][j], af[i], bf[j], acc[i][j]);
        }
        __syncthreads();
    }

    const int r = (bn >= T.start[3]) ? 3 : (bn >= T.start[2]) ? 2 : (bn >= T.start[1]) ? 1 : 0;
    float* fdst = T.f[r];
    __half* hdst = T.h[r];
    const int lcb = bn - T.start[r];
    const int stride = T.stride[r];

    float* wb = reinterpret_cast<float*>(sm) + warpId * 256;
#pragma unroll
    for (int i = 0; i < 4; i++)
#pragma unroll
        for (int j = 0; j < 2; j++) {
            wmma::store_matrix_sync(wb, acc[i][j], 16, wmma::mem_row_major);
            __syncwarp();
            const int r0 = bm + wm * 64 + i * 16;
            const int c0 = bn + wn * 32 + j * 16;
#pragma unroll
            for (int e = lane; e < 64; e += 32) {
                const int rr = e >> 2, c4 = (e & 3) * 4;
                if (r0 + rr >= M) continue;
                float4 vv = *reinterpret_cast<float4*>(wb + rr * 16 + c4);
                const int col = c0 + c4;
                vv.x += bias[col + 0];
                vv.y += bias[col + 1];
                vv.z += bias[col + 2];
                vv.w += bias[col + 3];
                const size_t o = (size_t)(r0 + rr) * stride + (lcb + (col - bn));
                if (fdst) {
                    *reinterpret_cast<float4*>(fdst + o) = vv;
                } else {
                    uint2 p;
                    *reinterpret_cast<__half2*>(&p.x) = __floats2half2_rn(vv.x, vv.y);
                    *reinterpret_cast<__half2*>(&p.y) = __floats2half2_rn(vv.z, vv.w);
                    *reinterpret_cast<uint2*>(hdst + o) = p;
                }
            }
            __syncwarp();
        }
}

// ---------------- CSR build ----------------
__global__ void scan_deg(const int* __restrict__ deg, int* __restrict__ ptr,
                         int* __restrict__ fill, int n)
{
    constexpr int PER = 10;
    const int tid = threadIdx.x;
    const int lane = tid & 31, wid = tid >> 5;
    const int base = tid * PER;

    int vals[PER];
    int s = 0;
#pragma unroll
    for (int i = 0; i < PER; i++) {
        const int idx = base + i;
        vals[i] = (idx < n) ? deg[idx] : 0;
        s += vals[i];
    }
    int sc = s;
#pragma unroll
    for (int o = 1; o < 32; o <<= 1) {
        int t = __shfl_up_sync(0xffffffffu, sc, o);
        if (lane >= o) sc += t;
    }
    __shared__ int wsum[32];
    if (lane == 31) wsum[wid] = sc;
    __syncthreads();
    if (wid == 0) {
        int w = wsum[lane];
#pragma unroll
        for (int o = 1; o < 32; o <<= 1) {
            int t = __shfl_up_sync(0xffffffffu, w, o);
            if (lane >= o) w += t;
        }
        wsum[lane] = w;
    }
    __syncthreads();
    int run = (sc - s) + (wid > 0 ? wsum[wid - 1] : 0);
#pragma unroll
    for (int i = 0; i < PER; i++) {
        const int idx = base + i;
        if (idx < n) { ptr[idx] = run; fill[idx] = run; }
        run += vals[i];
    }
    if (tid == 1023) ptr[n] = run;
}

__global__ void fill_csr(const int* __restrict__ ei, int* __restrict__ fill,
                         int* __restrict__ csr_src, int E)
{
    int e = blockIdx.x * blockDim.x + threadIdx.x;
    if (e < E) {
        const int d = ei[E + e];
        const int pos = atomicAdd(&fill[d], 1);
        csr_src[pos] = ei[e];
    }
}

// ---------------- layer-1 attention: 512 thr, 2 warps/head, unroll-2 ----------------
struct Edge1 { uint2 x; uint2 v[4]; float beta; };

__global__ __launch_bounds__(512)
void attn1_kernel(const float* __restrict__ z, const __half* __restrict__ x16,
                  const float* __restrict__ ex, const __half* __restrict__ v,
                  const int* __restrict__ ptr, const int* __restrict__ csr_src,
                  const float* __restrict__ skip, __half* __restrict__ outF16)
{
    constexpr int C = D1;
    constexpr int F4 = C / 128;
    __shared__ float smA[16 * C];      // 32KB: raw (odd warps) + merged (even regions)
    __shared__ float smM[16], smS[16];

    const int dst  = blockIdx.x;
    const int w    = threadIdx.x >> 5;   // 0..15
    const int head = w >> 1;
    const int p    = w & 1;
    const int lane = threadIdx.x & 31;
    const float scale = rsqrtf((float)C);

    const int beg = ptr[dst], end = ptr[dst + 1];
    const int mid = beg + ((end - beg + 1) >> 1);
    const int wb = p ? mid : beg;
    const int we = p ? end : mid;

    const float4 zr = reinterpret_cast<const float4*>(z + (size_t)dst * ZCOLS + head * F_IN)[lane];
    const float alpha = ex[(size_t)dst * 128 + head];

    float4 acc[F4];
#pragma unroll
    for (int i = 0; i < F4; i++) acc[i] = make_float4(0.f, 0.f, 0.f, 0.f);
    float m = -INFINITY, s = 0.f;

    auto load1 = [&](Edge1& E, int e, bool valid) {
        if (valid) {
            const int src = csr_src[e];
            E.x = reinterpret_cast<const uint2*>(x16 + (size_t)src * F_IN)[lane];
            const uint2* vrow = reinterpret_cast<const uint2*>(v + (size_t)src * (HEADS * C) + head * C);
#pragma unroll
            for (int i = 0; i < F4; i++) E.v[i] = vrow[lane + 32 * i];
            E.beta = ex[(size_t)src * 128 + 8 + head];
        } else {
            E.x = make_uint2(0, 0);
            E.beta = 0.f;
#pragma unroll
            for (int i = 0; i < F4; i++) E.v[i] = make_uint2(0, 0);
        }
    };
    auto dotx = [&](const uint2& xx) {
        const float2 x0 = __half22float2(*reinterpret_cast<const __half2*>(&xx.x));
        const float2 x1 = __half22float2(*reinterpret_cast<const __half2*>(&xx.y));
        return zr.x * x0.x + zr.y * x0.y + zr.z * x1.x + zr.w * x1.y;
    };

    Edge1 c0, c1, n0, n1;
    if (wb < we) {
        load1(c0, wb, true);
        load1(c1, wb + 1, wb + 1 < we);
    }

    for (int j = wb; j < we; j += 2) {
        if (j + 2 < we) {
            load1(n0, j + 2, true);
            load1(n1, j + 3, j + 3 < we);
        }
        float d1 = dotx(c0.x);
        float d2 = dotx(c1.x);
#pragma unroll
        for (int o = 16; o > 0; o >>= 1) {
            d1 += __shfl_xor_sync(0xffffffffu, d1, o);
            d2 += __shfl_xor_sync(0xffffffffu, d2, o);
        }
        const float a1 = (d1 + alpha + c0.beta) * scale;
        const float a2 = (j + 1 < we) ? (d2 + alpha + c1.beta) * scale : -INFINITY;
        const float mn = fmaxf(m, fmaxf(a1, a2));
        const float corr = expf(m - mn);
        const float w1 = expf(a1 - mn);
        const float w2 = expf(a2 - mn);
        s = s * corr + w1 + w2;
        m = mn;
#pragma unroll
        for (int i = 0; i < F4; i++) {
            const float2 u0 = __half22float2(*reinterpret_cast<const __half2*>(&c0.v[i].x));
            const float2 u1 = __half22float2(*reinterpret_cast<const __half2*>(&c0.v[i].y));
            const float2 q0 = __half22float2(*reinterpret_cast<const __half2*>(&c1.v[i].x));
            const float2 q1 = __half22float2(*reinterpret_cast<const __half2*>(&c1.v[i].y));
            acc[i].x = acc[i].x * corr + w1 * u0.x + w2 * q0.x;
            acc[i].y = acc[i].y * corr + w1 * u0.y + w2 * q0.y;
            acc[i].z = acc[i].z * corr + w1 * u1.x + w2 * q1.x;
            acc[i].w = acc[i].w * corr + w1 * u1.y + w2 * q1.y;
        }
        c0 = n0;
        c1 = n1;
    }

    // odd warps publish raw state
    if (p == 1) {
#pragma unroll
        for (int i = 0; i < F4; i++)
            *reinterpret_cast<float4*>(&smA[w * C + i * 128 + lane * 4]) = acc[i];
        if (lane == 0) { smM[w] = m; smS[w] = s; }
    }
    __syncthreads();

    // even warps merge and normalize into region (2*head)*C
    if (p == 0) {
        if (end > beg) {
            const float mp = smM[w + 1];
            const float sp = smS[w + 1];
            const float mstar = fmaxf(m, mp);
            const float c1f = expf(m - mstar);
            const float c2f = expf(mp - mstar);
            const float sstar = s * c1f + sp * c2f;
            const float inv = 1.f / (sstar + 1e-16f);
#pragma unroll
            for (int i = 0; i < F4; i++) {
                const float4 ap = *reinterpret_cast<const float4*>(&smA[(w + 1) * C + i * 128 + lane * 4]);
                float4 o;
                o.x = (acc[i].x * c1f + ap.x * c2f) * inv;
                o.y = (acc[i].y * c1f + ap.y * c2f) * inv;
                o.z = (acc[i].z * c1f + ap.z * c2f) * inv;
                o.w = (acc[i].w * c1f + ap.w * c2f) * inv;
                *reinterpret_cast<float4*>(&smA[w * C + i * 128 + lane * 4]) = o;
            }
        } else {
#pragma unroll
            for (int i = 0; i < F4; i++)
                *reinterpret_cast<float4*>(&smA[w * C + i * 128 + lane * 4]) =
                    make_float4(0.f, 0.f, 0.f, 0.f);
        }
    }
    __syncthreads();

    for (int f = threadIdx.x; f < C; f += 512) {
        float t = 0.f;
#pragma unroll
        for (int h = 0; h < HEADS; h++) t += smA[(2 * h) * C + f];
        t = t * (1.f / HEADS) + skip[(size_t)dst * C + f];
        t = (t > 0.f) ? t : expm1f(t);
        outF16[(size_t)dst * C + f] = __float2half(t);
    }
}

// ---------------- layers 2/3 attention: 512 thr, 2 warps/head ----------------
template <int C, bool F16OUT>
__global__ __launch_bounds__(512)
void attn_kernel(const float* __restrict__ q, const __half* __restrict__ k,
                 const __half* __restrict__ v, const int* __restrict__ ptr,
                 const int* __restrict__ csr_src, const float* __restrict__ skip,
                 float* __restrict__ out, __half* __restrict__ outF16,
                 const float* __restrict__ wg, const float* __restrict__ bg,
                 const int* __restrict__ batch, float* __restrict__ gate,
                 float* __restrict__ gmax)
{
    constexpr int H = HEADS;
    constexpr int F4 = C / 128;
    __shared__ float smA[16 * C];
    __shared__ float smM[16], smS[16];
    __shared__ float smG[512];

    const int dst  = blockIdx.x;
    const int w    = threadIdx.x >> 5;
    const int head = w >> 1;
    const int p    = w & 1;
    const int lane = threadIdx.x & 31;
    const float scale = rsqrtf((float)C);
    const size_t HC = (size_t)H * C;

    const int beg = ptr[dst], end = ptr[dst + 1];
    const int mid = beg + ((end - beg + 1) >> 1);
    const int wb = p ? mid : beg;
    const int we = p ? end : mid;

    const float4* qrow = reinterpret_cast<const float4*>(q + (size_t)dst * HC + head * C);
    float4 qr[F4], acc[F4];
#pragma unroll
    for (int i = 0; i < F4; i++) {
        qr[i] = qrow[lane + 32 * i];
        acc[i] = make_float4(0.f, 0.f, 0.f, 0.f);
    }
    float m = -INFINITY, s = 0.f;

    struct EdgeC { uint2 k[F4]; uint2 v[F4]; };
    auto loadE = [&](EdgeC& E, int e, bool valid) {
        if (valid) {
            const int src = csr_src[e];
            const uint2* krow = reinterpret_cast<const uint2*>(k + (size_t)src * HC + head * C);
            const uint2* vrow = reinterpret_cast<const uint2*>(v + (size_t)src * HC + head * C);
#pragma unroll
            for (int i = 0; i < F4; i++) { E.k[i] = krow[lane + 32 * i]; E.v[i] = vrow[lane + 32 * i]; }
        } else {
#pragma unroll
            for (int i = 0; i < F4; i++) { E.k[i] = make_uint2(0, 0); E.v[i] = make_uint2(0, 0); }
        }
    };
    auto dotk = [&](const EdgeC& E) {
        float d = 0.f;
#pragma unroll
        for (int i = 0; i < F4; i++) {
            const float2 k0 = __half22float2(*reinterpret_cast<const __half2*>(&E.k[i].x));
            const float2 k1 = __half22float2(*reinterpret_cast<const __half2*>(&E.k[i].y));
            d += qr[i].x * k0.x + qr[i].y * k0.y + qr[i].z * k1.x + qr[i].w * k1.y;
        }
        return d;
    };

    EdgeC c0, c1, n0, n1;
    if (wb < we) {
        loadE(c0, wb, true);
        loadE(c1, wb + 1, wb + 1 < we);
    }

    for (int j = wb; j < we; j += 2) {
        if (j + 2 < we) {
            loadE(n0, j + 2, true);
            loadE(n1, j + 3, j + 3 < we);
        }
        float d1 = dotk(c0);
        float d2 = dotk(c1);
#pragma unroll
        for (int o = 16; o > 0; o >>= 1) {
            d1 += __shfl_xor_sync(0xffffffffu, d1, o);
            d2 += __shfl_xor_sync(0xffffffffu, d2, o);
        }
        const float a1 = d1 * scale;
        const float a2 = (j + 1 < we) ? d2 * scale : -INFINITY;
        const float mn = fmaxf(m, fmaxf(a1, a2));
        const float corr = expf(m - mn);
        const float w1 = expf(a1 - mn);
        const float w2 = expf(a2 - mn);
        s = s * corr + w1 + w2;
        m = mn;
#pragma unroll
        for (int i = 0; i < F4; i++) {
            const float2 u0 = __half22float2(*reinterpret_cast<const __half2*>(&c0.v[i].x));
            const float2 u1 = __half22float2(*reinterpret_cast<const __half2*>(&c0.v[i].y));
            const float2 q0 = __half22float2(*reinterpret_cast<const __half2*>(&c1.v[i].x));
            const float2 q1 = __half22float2(*reinterpret_cast<const __half2*>(&c1.v[i].y));
            acc[i].x = acc[i].x * corr + w1 * u0.x + w2 * q0.x;
            acc[i].y = acc[i].y * corr + w1 * u0.y + w2 * q0.y;
            acc[i].z = acc[i].z * corr + w1 * u1.x + w2 * q1.x;
            acc[i].w = acc[i].w * corr + w1 * u1.y + w2 * q1.y;
        }
        c0 = n0;
        c1 = n1;
    }

    if (p == 1) {
#pragma unroll
        for (int i = 0; i < F4; i++)
            *reinterpret_cast<float4*>(&smA[w * C + i * 128 + lane * 4]) = acc[i];
        if (lane == 0) { smM[w] = m; smS[w] = s; }
    }
    __syncthreads();

    if (p == 0) {
        if (end > beg) {
            const float mp = smM[w + 1];
            const float sp = smS[w + 1];
            const float mstar = fmaxf(m, mp);
            const float c1f = expf(m - mstar);
            const float c2f = expf(mp - mstar);
            const float sstar = s * c1f + sp * c2f;
            const float inv = 1.f / (sstar + 1e-16f);
#pragma unroll
            for (int i = 0; i < F4; i++) {
                const float4 ap = *reinterpret_cast<const float4*>(&smA[(w + 1) * C + i * 128 + lane * 4]);
                float4 o;
                o.x = (acc[i].x * c1f + ap.x * c2f) * inv;
                o.y = (acc[i].y * c1f + ap.y * c2f) * inv;
                o.z = (acc[i].z * c1f + ap.z * c2f) * inv;
                o.w = (acc[i].w * c1f + ap.w * c2f) * inv;
                *reinterpret_cast<float4*>(&smA[w * C + i * 128 + lane * 4]) = o;
            }
        } else {
#pragma unroll
            for (int i = 0; i < F4; i++)
                *reinterpret_cast<float4*>(&smA[w * C + i * 128 + lane * 4]) =
                    make_float4(0.f, 0.f, 0.f, 0.f);
        }
    }
    __syncthreads();

    float part = 0.f;
    for (int f = threadIdx.x; f < C; f += 512) {
        float t = 0.f;
#pragma unroll
        for (int h = 0; h < H; h++) t += smA[(2 * h) * C + f];
        t = t * (1.f / H) + skip[(size_t)dst * C + f];
        t = (t > 0.f) ? t : expm1f(t);
        const size_t idx = (size_t)dst * C + f;
        if constexpr (F16OUT) {
            outF16[idx] = __float2half(t);
        } else {
            out[idx] = t;
            part += t * wg[f];
        }
    }

    if constexpr (!F16OUT) {
        __syncthreads();
        smG[threadIdx.x] = part;
        __syncthreads();
#pragma unroll
        for (int off = 256; off > 0; off >>= 1) {
            if (threadIdx.x < off) smG[threadIdx.x] += smG[threadIdx.x + off];
            __syncthreads();
        }
        if (threadIdx.x == 0) {
            const float d = smG[0] + bg[0];
            gate[dst] = d;
            float* addr = &gmax[batch[dst]];
            if (d >= 0.f) atomicMax((int*)addr, __float_as_int(d));
            else          atomicMin((unsigned int*)addr, __float_as_uint(d));
        }
    }
}

// ---------------- pooling + fc ----------------
__global__ void exp_pool(const float* __restrict__ h, const float* __restrict__ gate,
                         const int* __restrict__ batch, const float* __restrict__ gmax,
                         float* __restrict__ gsum, float* __restrict__ pool)
{
    const int node = blockIdx.x;
    const int f = threadIdx.x;
    const int b = batch[node];
    const float e = expf(gate[node] - gmax[b]);
    if (f == 0) atomicAdd(&gsum[b], e);
    atomicAdd(&pool[b * D3 + f], e * h[(size_t)node * D3 + f]);
}

__global__ void fc_kernel(const float* __restrict__ pool, const float* __restrict__ gsum,
                          const float* __restrict__ wfc, const float* __restrict__ bfc,
                          float* __restrict__ out)
{
    const int t = threadIdx.x;
    if (t >= N_GRAPHS * OUT_DIM) return;
    const int g = t / OUT_DIM, o = t % OUT_DIM;
    float s = 0.f;
#pragma unroll 16
    for (int f = 0; f < D3; f++) s += pool[g * D3 + f] * wfc[f * OUT_DIM + o];
    out[g * OUT_DIM + o] = s / (gsum[g] + 1e-16f) + bfc[o];
}

// ---------------- launch ----------------
extern "C" void kernel_launch(void* const* d_in, const int* in_sizes, int n_in,
                              void* d_out, int out_size)
{
    const float* x     = (const float*)d_in[0];
    const int*   ei    = (const int*)d_in[1];
    const int*   batch = (const int*)d_in[2];
    const float* W[12] = { (const float*)d_in[3],  (const float*)d_in[5],
                           (const float*)d_in[7],  (const float*)d_in[9],
                           (const float*)d_in[11], (const float*)d_in[13],
                           (const float*)d_in[15], (const float*)d_in[17],
                           (const float*)d_in[19], (const float*)d_in[21],
                           (const float*)d_in[23], (const float*)d_in[25] };
    const float* Bv[12] = { (const float*)d_in[4],  (const float*)d_in[6],
                            (const float*)d_in[8],  (const float*)d_in[10],
                            (const float*)d_in[12], (const float*)d_in[14],
                            (const float*)d_in[16], (const float*)d_in[18],
                            (const float*)d_in[20], (const float*)d_in[22],
                            (const float*)d_in[24], (const float*)d_in[26] };
    const float* w_g  = (const float*)d_in[27]; const float* b_g  = (const float*)d_in[28];
    const float* w_fc = (const float*)d_in[29]; const float* b_fc = (const float*)d_in[30];
    float* out = (float*)d_out;

    float *qb, *skipb, *hA, *gateb, *gmaxb, *gsumb, *poolb, *biasb, *extrasb;
    __half *kb, *vb, *x16b, *Af16b, *WFb, *A16b, *BT16b;
    int *degb, *ptrb, *fillb, *csrb;
    cudaGetSymbolAddress((void**)&qb,     g_q);
    cudaGetSymbolAddress((void**)&kb,     g_k);
    cudaGetSymbolAddress((void**)&vb,     g_v);
    cudaGetSymbolAddress((void**)&skipb,  g_skip);
    cudaGetSymbolAddress((void**)&hA,     g_hA);
    cudaGetSymbolAddress((void**)&extrasb,g_extras);
    cudaGetSymbolAddress((void**)&x16b,   g_x16);
    cudaGetSymbolAddress((void**)&Af16b,  g_Af16);
    cudaGetSymbolAddress((void**)&A16b,   g_A16);
    cudaGetSymbolAddress((void**)&BT16b,  g_BT16);
    cudaGetSymbolAddress((void**)&WFb,    g_WF);
    cudaGetSymbolAddress((void**)&biasb,  g_bias);
    cudaGetSymbolAddress((void**)&degb,   g_deg);
    cudaGetSymbolAddress((void**)&ptrb,   g_ptr);
    cudaGetSymbolAddress((void**)&fillb,  g_fill);
    cudaGetSymbolAddress((void**)&csrb,   g_csr_src);
    cudaGetSymbolAddress((void**)&gateb,  g_gate);
    cudaGetSymbolAddress((void**)&gmaxb,  g_gmax);
    cudaGetSymbolAddress((void**)&gsumb,  g_gsum);
    cudaGetSymbolAddress((void**)&poolb,  g_pool);

    const int N = N_NODES, E = N_EDGES;

    // ---- pack regions ----
    PackArgs P;
    long long wcum = 0;
    int bcum = 0;
    int ri = 0;
    auto addW = [&](const float* src, int K, int ncols, long long base, int ntot, int coff,
                    const float* bsrc, int boff) {
        P.wsrc[ri] = src; P.wcum[ri] = wcum; P.wncols[ri] = ncols;
        P.wdstBase[ri] = base; P.wntot[ri] = ntot; P.wcoff[ri] = coff;
        wcum += (long long)K * ncols;
        P.bsrc[ri] = bsrc; P.bcum[ri] = bcum; P.boff[ri] = boff;
        bcum += ncols;
        ri++;
    };
    addW(W[2], F_IN, HEADS * D1, WF_BASE1, F_N1, MCOLS, Bv[2], BB1 + MCOLS);
    addW(W[3], F_IN, D1, WF_BASE1, F_N1, MCOLS + HEADS * D1, Bv[3], BB1 + MCOLS + HEADS * D1);
    for (int p = 0; p < 4; p++) {
        const int ncols = (p < 3) ? HEADS * D2 : D2;
        const int coff = (p < 3) ? p * HEADS * D2 : 3 * HEADS * D2;
        addW(W[4 + p], D1, ncols, WF_BASE2, F_N2, coff, Bv[4 + p], BB2 + coff);
    }
    for (int p = 0; p < 4; p++) {
        const int ncols = (p < 3) ? HEADS * D3 : D3;
        const int coff = (p < 3) ? p * HEADS * D3 : 3 * HEADS * D3;
        addW(W[8 + p], D2, ncols, WF_BASE3, F_N3, coff, Bv[8 + p], BB3 + coff);
    }
    P.wcum[ri] = wcum;
    P.bcum[ri] = bcum;
    for (int r2 = ri; r2 < 12; r2++) { P.wcum[r2 + 1] = wcum; P.bcum[r2 + 1] = bcum; }
    P.x = x;
    P.wq = W[0];
    P.wk = W[1];
    P.ei = ei;

    const long long packTotal = wcum + NXTOT + bcum + QKTOT + E + POOLINIT;
    const int gy = (N + 127) / 128;

    // epilogue tables
    EpiTab T1;
    T1.start[0] = 0;     T1.f[0] = qb;      T1.h[0] = nullptr; T1.stride[0] = ZCOLS;
    T1.start[1] = ZCOLS; T1.f[1] = extrasb; T1.h[1] = nullptr; T1.stride[1] = 128;
    T1.start[2] = MCOLS; T1.f[2] = nullptr; T1.h[2] = vb;      T1.stride[2] = HEADS * D1;
    T1.start[3] = MCOLS + HEADS * D1; T1.f[3] = skipb; T1.h[3] = nullptr; T1.stride[3] = D1;
    EpiTab T2;
    T2.start[0] = 0;              T2.f[0] = qb;      T2.h[0] = nullptr; T2.stride[0] = HEADS * D2;
    T2.start[1] = HEADS * D2;     T2.f[1] = nullptr; T2.h[1] = kb;      T2.stride[1] = HEADS * D2;
    T2.start[2] = 2 * HEADS * D2; T2.f[2] = nullptr; T2.h[2] = vb;      T2.stride[2] = HEADS * D2;
    T2.start[3] = 3 * HEADS * D2; T2.f[3] = skipb;   T2.h[3] = nullptr; T2.stride[3] = D2;
    EpiTab T3;
    T3.start[0] = 0;              T3.f[0] = qb;      T3.h[0] = nullptr; T3.stride[0] = HEADS * D3;
    T3.start[1] = HEADS * D3;     T3.f[1] = nullptr; T3.h[1] = kb;      T3.stride[1] = HEADS * D3;
    T3.start[2] = 2 * HEADS * D3; T3.f[2] = nullptr; T3.h[2] = vb;      T3.stride[2] = HEADS * D3;
    T3.start[3] = 3 * HEADS * D3; T3.f[3] = skipb;   T3.h[3] = nullptr; T3.stride[3] = D3;

    // launch order: gemm_half L1 at slot 5 (ncu capture)
    cudaMemsetAsync(degb, 0, N * sizeof(int));                                          // 1
    pack_all<<<(int)((packTotal + 255) / 256), 256>>>(P, WFb, x16b, biasb, A16b, BT16b,
                                                      degb, gmaxb, gsumb, poolb,
                                                      wcum, NXTOT, bcum);               // 2
    make_m_mm<<<dim3(1, 8), 256>>>(A16b, BT16b, WFb);                                   // 3
    m_extras<<<MCOLS, 128>>>(W[0], W[1], Bv[0], Bv[1], WFb, biasb + BB1);               // 4
    gemm_half<<<dim3(F_N1 / 128, gy), 256>>>(x16b, WFb + WF_BASE1,
                                             biasb + BB1, T1, N, F_N1, F_IN);           // 5 <- profiled
    scan_deg<<<1, 1024>>>(degb, ptrb, fillb, N);                                        // 6
    fill_csr<<<(E + 255) / 256, 256>>>(ei, fillb, csrb, E);                             // 7
    attn1_kernel<<<N, 512>>>(qb, x16b, extrasb, vb, ptrb, csrb, skipb, Af16b);          // 8

    gemm_half<<<dim3(F_N2 / 128, gy), 256>>>(Af16b, WFb + WF_BASE2,
                                             biasb + BB2, T2, N, F_N2, D1);
    attn_kernel<D2, true><<<N, 512>>>(qb, kb, vb, ptrb, csrb, skipb, nullptr, Af16b,
                                      nullptr, nullptr, nullptr, nullptr, nullptr);

    gemm_half<<<dim3(F_N3 / 128, gy), 256>>>(Af16b, WFb + WF_BASE3,
                                             biasb + BB3, T3, N, F_N3, D2);
    attn_kernel<D3, false><<<N, 512>>>(qb, kb, vb, ptrb, csrb, skipb, hA, nullptr,
                                       w_g, b_g, batch, gateb, gmaxb);

    exp_pool<<<N, D3>>>(hA, gateb, batch, gmaxb, gsumb, poolb);
    fc_kernel<<<1, 1024>>>(poolb, gsumb, w_fc, b_fc, out);
}

// round 17
// speedup vs baseline: 1.2066x; 1.2066x over previous
#include <cuda_runtime.h>
#include <cuda_fp16.h>
#include <mma.h>
#include <math.h>
#include <stdint.h>

using namespace nvcuda;

// ---------------- problem constants ----------------
#define N_NODES 10000
#define N_EDGES 80000
#define N_GRAPHS 64
#define HEADS 8
#define F_IN 128
#define D1 512
#define D2 256
#define D3 128
#define OUT_DIM 10

#define ZCOLS (HEADS * F_IN)          // 1024
#define MCOLS (ZCOLS + 128)           // 1152

#define F_N1 (MCOLS + HEADS * D1 + D1)   // 5760
#define F_N2 (3 * HEADS * D2 + D2)       // 6400
#define F_N3 (3 * HEADS * D3 + D3)       // 3200
#define WF_BASE1 0LL
#define WF_BASE2 ((long long)F_IN * F_N1)
#define WF_BASE3 (WF_BASE2 + (long long)D1 * F_N2)
#define WF_TOTAL (WF_BASE3 + (long long)D2 * F_N3)

#define BB1 0
#define BB2 F_N1
#define BB3 (BB2 + F_N2)
#define BTOTAL (BB3 + F_N3)
#define NXTOT (N_NODES * F_IN)
#define QKTOT (2 * F_IN * HEADS * D1)    // 1048576
#define POOLINIT (N_GRAPHS + N_GRAPHS + N_GRAPHS * D3)
#define EXTOT (MCOLS + 128 * 128)        // L1 bias row + extras columns

// ---------------- device scratch (static, no allocs) ----------------
__device__ float g_q[(size_t)N_NODES * (HEADS * D1)];
__device__ __half g_k[(size_t)N_NODES * (HEADS * D1)];
__device__ __half g_v[(size_t)N_NODES * (HEADS * D1)];
__device__ float g_skip[(size_t)N_NODES * D1];
__device__ float g_hA[(size_t)N_NODES * D1];

__device__ float g_extras[(size_t)N_NODES * 128];
__device__ __half g_x16[(size_t)N_NODES * F_IN];
__device__ __half g_Af16[(size_t)N_NODES * D1];

__device__ __half g_A16[8 * 128 * 512];
__device__ __half g_BT16[8 * 512 * 128];

__device__ __half g_WF[WF_TOTAL];
__device__ float g_bias[BTOTAL];

__device__ int g_deg[N_NODES];
__device__ int g_ptr[N_NODES + 1];
__device__ int g_fill[N_NODES];
__device__ int g_csr_src[N_EDGES];

__device__ float g_gate[N_NODES];
__device__ float g_gmax[N_GRAPHS];
__device__ float g_gsum[N_GRAPHS];
__device__ float g_pool[N_GRAPHS * D3];

// ---------------- cp.async helpers ----------------
__device__ __forceinline__ void cp16(uint32_t dst, const void* src)
{
    asm volatile("cp.async.cg.shared.global [%0], [%1], 16;" :: "r"(dst), "l"(src));
}
__device__ __forceinline__ void cp_commit() { asm volatile("cp.async.commit_group;"); }
template <int Np>
__device__ __forceinline__ void cp_wait() { asm volatile("cp.async.wait_group %0;" :: "n"(Np)); }

// ---------------- one-shot packing ----------------
struct PackArgs {
    const float* wsrc[12];
    long long wcum[13];
    int wncols[12];
    long long wdstBase[12];
    int wntot[12];
    int wcoff[12];
    const float* bsrc[12];
    int bcum[13];
    int boff[12];
    const float* x;
    const float* wq;
    const float* wk;
    const float* bq;
    const float* bk;
    const int* ei;
};

__global__ void pack_all(PackArgs P, __half* __restrict__ WF, __half* __restrict__ x16,
                         float* __restrict__ bias, __half* __restrict__ A16,
                         __half* __restrict__ BT16, int* __restrict__ deg,
                         float* __restrict__ gmax, float* __restrict__ gsum,
                         float* __restrict__ pool,
                         long long wtotal, long long xtotal, int btotal)
{
    long long i = (long long)blockIdx.x * blockDim.x + threadIdx.x;
    if (i < wtotal) {
        int r = 0;
        while (i >= P.wcum[r + 1]) r++;
        const long long li = i - P.wcum[r];
        const int nc = P.wncols[r];
        const int k = (int)(li / nc), c = (int)(li % nc);
        const long long di = P.wdstBase[r] + (long long)k * P.wntot[r] + P.wcoff[r] + c;
        WF[di] = __float2half(P.wsrc[r][li]);
        return;
    }
    i -= wtotal;
    if (i < xtotal) {
        x16[i] = __float2half(P.x[i]);
        return;
    }
    i -= xtotal;
    if (i < btotal) {
        int j = (int)i;
        int r = 0;
        while (j >= P.bcum[r + 1]) r++;
        bias[P.boff[r] + (j - P.bcum[r])] = P.bsrc[r][j - P.bcum[r]];
        return;
    }
    i -= btotal;
    if (i < QKTOT) {
        if (i < QKTOT / 2) {
            const int idx = (int)i;
            const int k = idx >> 12, c = idx & 4095;
            const int h = c >> 9, cc = c & 511;
            A16[(size_t)h * 65536 + k * 512 + cc] = __float2half(P.wq[idx]);
        } else {
            const int idx = (int)(i - QKTOT / 2);
            const int j = idx >> 12, c = idx & 4095;
            const int h = c >> 9, cc = c & 511;
            BT16[(size_t)h * 65536 + cc * 128 + j] = __float2half(P.wk[idx]);
        }
        return;
    }
    i -= QKTOT;
    if (i < N_EDGES) {
        atomicAdd(&deg[P.ei[N_EDGES + (int)i]], 1);
        return;
    }
    i -= N_EDGES;
    if (i < POOLINIT) {
        const int j = (int)i;
        if (j < N_GRAPHS) gmax[j] = -INFINITY;
        else if (j < 2 * N_GRAPHS) gsum[j - N_GRAPHS] = 0.f;
        else pool[j - 2 * N_GRAPHS] = 0.f;
        return;
    }
    i -= POOLINIT;
    // ---- L1 extras: bias row + alpha/beta/zero weight columns ----
    if (i < MCOLS) {
        const int j = (int)i;
        float bval = 0.f;
        if (j >= 1024 && j < 1032) {
            const int base = (j - 1024) * D1;
            float p = 0.f;
#pragma unroll 4
            for (int c = 0; c < D1; c++) p += P.bq[base + c] * P.bk[base + c];
            bval = p;
        }
        bias[BB1 + j] = bval;
        return;
    }
    i -= MCOLS;
    if (i < 128 * 128) {
        const int r = (int)(i >> 7);        // input-feature row 0..127
        const int c = (int)(i & 127);       // extras column 0..127
        const int j = ZCOLS + c;
        float acc = 0.f;
        if (j < 1032) {                     // alpha col: wq[r]·bk (head h)
            const int base = (j - 1024) * D1;
            const float* row = P.wq + (size_t)r * (HEADS * D1) + base;
            const float* vec = P.bk + base;
#pragma unroll 4
            for (int cc = 0; cc < D1; cc++) acc += row[cc] * vec[cc];
        } else if (j < 1040) {              // beta col: wk[r]·bq
            const int base = (j - 1032) * D1;
            const float* row = P.wk + (size_t)r * (HEADS * D1) + base;
            const float* vec = P.bq + base;
#pragma unroll 4
            for (int cc = 0; cc < D1; cc++) acc += row[cc] * vec[cc];
        }
        WF[WF_BASE1 + (size_t)r * F_N1 + j] = __float2half(acc);
    }
}

// ---------------- batched per-head MM: M_h = Wq_h @ Wk_h^T ----------------
#define LDAH 40
#define LDBH 136
#define ASZH (128 * LDAH)
#define BSZH (32 * LDBH)
#define STAGE_H (ASZH + BSZH)

__global__ __launch_bounds__(256, 2)
void make_m_mm(const __half* __restrict__ A16, const __half* __restrict__ BT16,
               __half* __restrict__ WF)
{
    __shared__ __align__(16) __half sm[2 * STAGE_H];

    const int tid = threadIdx.x;
    const int warpId = tid >> 5;
    const int lane = tid & 31;
    const int wm = warpId >> 2;
    const int wn = warpId & 3;
    const int h = blockIdx.y;
    const __half* A = A16 + (size_t)h * 128 * 512;
    const __half* B = BT16 + (size_t)h * 512 * 128;
    constexpr int K = 512, N = 128;

    const int ar = tid >> 1, ac = (tid & 1) * 16;
    const int br = tid >> 3, bc = (tid & 7) * 16;

    wmma::fragment<wmma::accumulator, 16, 16, 16, float> acc[4][2];
#pragma unroll
    for (int i = 0; i < 4; i++)
#pragma unroll
        for (int j = 0; j < 2; j++) wmma::fill_fragment(acc[i][j], 0.f);

    auto issue = [&](int kb, int s) {
        __half* base = sm + s * STAGE_H;
        __half* pA = base + ar * LDAH + ac;
        const size_t off = (size_t)ar * K + kb + ac;
        cp16((uint32_t)__cvta_generic_to_shared(pA),     A + off);
        cp16((uint32_t)__cvta_generic_to_shared(pA + 8), A + off + 8);
        __half* pB = base + ASZH + br * LDBH + bc;
        const size_t boff = (size_t)(kb + br) * N + bc;
        cp16((uint32_t)__cvta_generic_to_shared(pB),     B + boff);
        cp16((uint32_t)__cvta_generic_to_shared(pB + 8), B + boff + 8);
        cp_commit();
    };

    const int nk = K >> 5;
    issue(0, 0);

    for (int it = 0; it < nk; ++it) {
        const int s = it & 1;
        if (it + 1 < nk) { issue((it + 1) << 5, s ^ 1); cp_wait<1>(); }
        else             { cp_wait<0>(); }
        __syncthreads();

        const __half* As = sm + s * STAGE_H;
        const __half* Bs = As + ASZH;

#pragma unroll
        for (int kk = 0; kk < 2; kk++) {
            wmma::fragment<wmma::matrix_a, 16, 16, 16, __half, wmma::row_major> af[4];
            wmma::fragment<wmma::matrix_b, 16, 16, 16, __half, wmma::row_major> bf[2];
#pragma unroll
            for (int i = 0; i < 4; i++)
                wmma::load_matrix_sync(af[i], As + (wm * 64 + i * 16) * LDAH + kk * 16, LDAH);
#pragma unroll
            for (int j = 0; j < 2; j++)
                wmma::load_matrix_sync(bf[j], Bs + (kk * 16) * LDBH + wn * 32 + j * 16, LDBH);
#pragma unroll
            for (int i = 0; i < 4; i++)
#pragma unroll
                for (int j = 0; j < 2; j++)
                    wmma::mma_sync(acc[i][j], af[i], bf[j], acc[i][j]);
        }
        __syncthreads();
    }

    float* wb = reinterpret_cast<float*>(sm) + warpId * 256;
#pragma unroll
    for (int i = 0; i < 4; i++)
#pragma unroll
        for (int j = 0; j < 2; j++) {
            wmma::store_matrix_sync(wb, acc[i][j], 16, wmma::mem_row_major);
            __syncwarp();
            const int r0 = wm * 64 + i * 16;
            const int c0 = wn * 32 + j * 16;
#pragma unroll
            for (int e = lane; e < 64; e += 32) {
                const int rr = e >> 2, c4 = (e & 3) * 4;
                const float4 vv = *reinterpret_cast<float4*>(wb + rr * 16 + c4);
                uint2 p;
                *reinterpret_cast<__half2*>(&p.x) = __floats2half2_rn(vv.x, vv.y);
                *reinterpret_cast<__half2*>(&p.y) = __floats2half2_rn(vv.z, vv.w);
                *reinterpret_cast<uint2*>(&WF[WF_BASE1 + (size_t)(r0 + rr) * F_N1
                                              + h * 128 + c0 + c4]) = p;
            }
            __syncwarp();
        }
}

// ---------------- epilogue routing table ----------------
struct EpiTab {
    float* f[4];
    __half* h[4];
    int stride[4];
    int start[4];
};

// ---------------- fp16 single-pass GEMM, BK=32 ----------------
__global__ __launch_bounds__(256, 2)
void gemm_half(const __half* __restrict__ A, const __half* __restrict__ B,
               const float* __restrict__ bias, EpiTab T,
               int M, int N, int K)
{
    __shared__ __align__(16) __half sm[2 * STAGE_H];

    const int tid = threadIdx.x;
    const int warpId = tid >> 5;
    const int lane = tid & 31;
    const int wm = warpId >> 2;
    const int wn = warpId & 3;
    const int bm = blockIdx.y * 128;
    const int bn = blockIdx.x * 128;

    const int ar = tid >> 1, ac = (tid & 1) * 16;
    const int br = tid >> 3, bc = (tid & 7) * 16;

    wmma::fragment<wmma::accumulator, 16, 16, 16, float> acc[4][2];
#pragma unroll
    for (int i = 0; i < 4; i++)
#pragma unroll
        for (int j = 0; j < 2; j++) wmma::fill_fragment(acc[i][j], 0.f);

    auto issue = [&](int kb, int s) {
        __half* base = sm + s * STAGE_H;
        __half* pA = base + ar * LDAH + ac;
        const int gr = bm + ar;
        if (gr < M) {
            const size_t off = (size_t)gr * K + kb + ac;
            cp16((uint32_t)__cvta_generic_to_shared(pA),     A + off);
            cp16((uint32_t)__cvta_generic_to_shared(pA + 8), A + off + 8);
        } else {
            uint4 z = make_uint4(0, 0, 0, 0);
            *reinterpret_cast<uint4*>(pA) = z;
            *reinterpret_cast<uint4*>(pA + 8) = z;
        }
        __half* pB = base + ASZH + br * LDBH + bc;
        const size_t boff = (size_t)(kb + br) * N + bn + bc;
        cp16((uint32_t)__cvta_generic_to_shared(pB),     B + boff);
        cp16((uint32_t)__cvta_generic_to_shared(pB + 8), B + boff + 8);
        cp_commit();
    };

    const int nk = K >> 5;
    issue(0, 0);

    for (int it = 0; it < nk; ++it) {
        const int s = it & 1;
        if (it + 1 < nk) { issue((it + 1) << 5, s ^ 1); cp_wait<1>(); }
        else             { cp_wait<0>(); }
        __syncthreads();

        const __half* As = sm + s * STAGE_H;
        const __half* Bs = As + ASZH;

#pragma unroll
        for (int kk = 0; kk < 2; kk++) {
            wmma::fragment<wmma::matrix_a, 16, 16, 16, __half, wmma::row_major> af[4];
            wmma::fragment<wmma::matrix_b, 16, 16, 16, __half, wmma::row_major> bf[2];
#pragma unroll
            for (int i = 0; i < 4; i++)
                wmma::load_matrix_sync(af[i], As + (wm * 64 + i * 16) * LDAH + kk * 16, LDAH);
#pragma unroll
            for (int j = 0; j < 2; j++)
                wmma::load_matrix_sync(bf[j], Bs + (kk * 16) * LDBH + wn * 32 + j * 16, LDBH);
#pragma unroll
            for (int i = 0; i < 4; i++)
#pragma unroll
                for (int j = 0; j < 2; j++)
                    wmma::mma_sync(acc[i][j], af[i], bf[j], acc[i][j]);
        }
        __syncthreads();
    }

    const int r = (bn >= T.start[3]) ? 3 : (bn >= T.start[2]) ? 2 : (bn >= T.start[1]) ? 1 : 0;
    float* fdst = T.f[r];
    __half* hdst = T.h[r];
    const int lcb = bn - T.start[r];
    const int stride = T.stride[r];

    float* wb = reinterpret_cast<float*>(sm) + warpId * 256;
#pragma unroll
    for (int i = 0; i < 4; i++)
#pragma unroll
        for (int j = 0; j < 2; j++) {
            wmma::store_matrix_sync(wb, acc[i][j], 16, wmma::mem_row_major);
            __syncwarp();
            const int r0 = bm + wm * 64 + i * 16;
            const int c0 = bn + wn * 32 + j * 16;
#pragma unroll
            for (int e = lane; e < 64; e += 32) {
                const int rr = e >> 2, c4 = (e & 3) * 4;
                if (r0 + rr >= M) continue;
                float4 vv = *reinterpret_cast<float4*>(wb + rr * 16 + c4);
                const int col = c0 + c4;
                vv.x += bias[col + 0];
                vv.y += bias[col + 1];
                vv.z += bias[col + 2];
                vv.w += bias[col + 3];
                const size_t o = (size_t)(r0 + rr) * stride + (lcb + (col - bn));
                if (fdst) {
                    *reinterpret_cast<float4*>(fdst + o) = vv;
                } else {
                    uint2 p;
                    *reinterpret_cast<__half2*>(&p.x) = __floats2half2_rn(vv.x, vv.y);
                    *reinterpret_cast<__half2*>(&p.y) = __floats2half2_rn(vv.z, vv.w);
                    *reinterpret_cast<uint2*>(hdst + o) = p;
                }
            }
            __syncwarp();
        }
}

// ---------------- CSR build ----------------
__global__ void scan_deg(const int* __restrict__ deg, int* __restrict__ ptr,
                         int* __restrict__ fill, int n)
{
    constexpr int PER = 10;
    const int tid = threadIdx.x;
    const int lane = tid & 31, wid = tid >> 5;
    const int base = tid * PER;

    int vals[PER];
    int s = 0;
#pragma unroll
    for (int i = 0; i < PER; i++) {
        const int idx = base + i;
        vals[i] = (idx < n) ? deg[idx] : 0;
        s += vals[i];
    }
    int sc = s;
#pragma unroll
    for (int o = 1; o < 32; o <<= 1) {
        int t = __shfl_up_sync(0xffffffffu, sc, o);
        if (lane >= o) sc += t;
    }
    __shared__ int wsum[32];
    if (lane == 31) wsum[wid] = sc;
    __syncthreads();
    if (wid == 0) {
        int w = wsum[lane];
#pragma unroll
        for (int o = 1; o < 32; o <<= 1) {
            int t = __shfl_up_sync(0xffffffffu, w, o);
            if (lane >= o) w += t;
        }
        wsum[lane] = w;
    }
    __syncthreads();
    int run = (sc - s) + (wid > 0 ? wsum[wid - 1] : 0);
#pragma unroll
    for (int i = 0; i < PER; i++) {
        const int idx = base + i;
        if (idx < n) { ptr[idx] = run; fill[idx] = run; }
        run += vals[i];
    }
    if (tid == 1023) ptr[n] = run;
}

__global__ void fill_csr(const int* __restrict__ ei, int* __restrict__ fill,
                         int* __restrict__ csr_src, int E)
{
    int e = blockIdx.x * blockDim.x + threadIdx.x;
    if (e < E) {
        const int d = ei[E + e];
        const int pos = atomicAdd(&fill[d], 1);
        csr_src[pos] = ei[e];
    }
}

// ---------------- layer-1 attention (factored logits, unroll-2, predicated) ----------------
struct Edge1 { uint2 x; uint2 v[4]; float beta; };

__global__ void attn1_kernel(const float* __restrict__ z, const __half* __restrict__ x16,
                             const float* __restrict__ ex, const __half* __restrict__ v,
                             const int* __restrict__ ptr, const int* __restrict__ csr_src,
                             const float* __restrict__ skip,
                             __half* __restrict__ outF16)
{
    constexpr int C = D1;
    constexpr int F4 = C / 128;
    __shared__ float red[HEADS * C];

    const int dst  = blockIdx.x;
    const int warp = threadIdx.x >> 5;
    const int lane = threadIdx.x & 31;
    const float scale = rsqrtf((float)C);

    const int beg = ptr[dst], end = ptr[dst + 1];

    const float4 zr = reinterpret_cast<const float4*>(z + (size_t)dst * ZCOLS + warp * F_IN)[lane];
    const float alpha = ex[(size_t)dst * 128 + warp];

    float4 acc[F4];
#pragma unroll
    for (int i = 0; i < F4; i++) acc[i] = make_float4(0.f, 0.f, 0.f, 0.f);
    float m = -INFINITY, s = 0.f;

    auto load1 = [&](Edge1& E, int e, bool valid) {
        if (valid) {
            const int src = csr_src[e];
            E.x = reinterpret_cast<const uint2*>(x16 + (size_t)src * F_IN)[lane];
            const uint2* vrow = reinterpret_cast<const uint2*>(v + (size_t)src * (HEADS * C) + warp * C);
#pragma unroll
            for (int i = 0; i < F4; i++) E.v[i] = vrow[lane + 32 * i];
            E.beta = ex[(size_t)src * 128 + 8 + warp];
        } else {
            E.x = make_uint2(0, 0);
            E.beta = 0.f;
#pragma unroll
            for (int i = 0; i < F4; i++) E.v[i] = make_uint2(0, 0);
        }
    };
    auto dotx = [&](const uint2& xx) {
        const float2 x0 = __half22float2(*reinterpret_cast<const __half2*>(&xx.x));
        const float2 x1 = __half22float2(*reinterpret_cast<const __half2*>(&xx.y));
        return zr.x * x0.x + zr.y * x0.y + zr.z * x1.x + zr.w * x1.y;
    };

    Edge1 c0, c1, n0, n1;
    if (beg < end) {
        load1(c0, beg, true);
        load1(c1, beg + 1, beg + 1 < end);
    }

    for (int j = beg; j < end; j += 2) {
        if (j + 2 < end) {
            load1(n0, j + 2, true);
            load1(n1, j + 3, j + 3 < end);
        }
        float d1 = dotx(c0.x);
        float d2 = dotx(c1.x);
#pragma unroll
        for (int o = 16; o > 0; o >>= 1) {
            d1 += __shfl_xor_sync(0xffffffffu, d1, o);
            d2 += __shfl_xor_sync(0xffffffffu, d2, o);
        }
        const float a1 = (d1 + alpha + c0.beta) * scale;
        const float a2 = (j + 1 < end) ? (d2 + alpha + c1.beta) * scale : -INFINITY;
        const float mn = fmaxf(m, fmaxf(a1, a2));
        const float corr = expf(m - mn);
        const float w1 = expf(a1 - mn);
        const float w2 = expf(a2 - mn);
        s = s * corr + w1 + w2;
        m = mn;
#pragma unroll
        for (int i = 0; i < F4; i++) {
            const float2 u0 = __half22float2(*reinterpret_cast<const __half2*>(&c0.v[i].x));
            const float2 u1 = __half22float2(*reinterpret_cast<const __half2*>(&c0.v[i].y));
            const float2 w0 = __half22float2(*reinterpret_cast<const __half2*>(&c1.v[i].x));
            const float2 w1v = __half22float2(*reinterpret_cast<const __half2*>(&c1.v[i].y));
            acc[i].x = acc[i].x * corr + w1 * u0.x + w2 * w0.x;
            acc[i].y = acc[i].y * corr + w1 * u0.y + w2 * w0.y;
            acc[i].z = acc[i].z * corr + w1 * u1.x + w2 * w1v.x;
            acc[i].w = acc[i].w * corr + w1 * u1.y + w2 * w1v.y;
        }
        c0 = n0;
        c1 = n1;
    }

    const float inv = (end > beg) ? (1.f / (s + 1e-16f)) : 0.f;
#pragma unroll
    for (int i = 0; i < F4; i++) {
        float4 o = make_float4(acc[i].x * inv, acc[i].y * inv, acc[i].z * inv, acc[i].w * inv);
        *reinterpret_cast<float4*>(&red[warp * C + i * 128 + lane * 4]) = o;
    }
    __syncthreads();

    for (int f = threadIdx.x; f < C; f += blockDim.x) {
        float t = 0.f;
#pragma unroll
        for (int h = 0; h < HEADS; h++) t += red[h * C + f];
        t = t * (1.f / HEADS) + skip[(size_t)dst * C + f];
        t = (t > 0.f) ? t : expm1f(t);
        outF16[(size_t)dst * C + f] = __float2half(t);
    }
}

// ---------------- layers 2/3 attention (unroll-2, predicated; optional fused gate) ----------------
template <int C, bool F16OUT>
__global__ void attn_kernel(const float* __restrict__ q, const __half* __restrict__ k,
                            const __half* __restrict__ v, const int* __restrict__ ptr,
                            const int* __restrict__ csr_src, const float* __restrict__ skip,
                            float* __restrict__ out, __half* __restrict__ outF16,
                            const float* __restrict__ wg, const float* __restrict__ bg,
                            const int* __restrict__ batch, float* __restrict__ gate,
                            float* __restrict__ gmax)
{
    constexpr int H = HEADS;
    constexpr int F4 = C / 128;
    __shared__ float red[H * C];

    const int dst  = blockIdx.x;
    const int warp = threadIdx.x >> 5;
    const int lane = threadIdx.x & 31;
    const float scale = rsqrtf((float)C);
    const size_t HC = (size_t)H * C;

    const int beg = ptr[dst], end = ptr[dst + 1];

    const float4* qrow = reinterpret_cast<const float4*>(q + (size_t)dst * HC + warp * C);
    float4 qr[F4], acc[F4];
#pragma unroll
    for (int i = 0; i < F4; i++) {
        qr[i] = qrow[lane + 32 * i];
        acc[i] = make_float4(0.f, 0.f, 0.f, 0.f);
    }
    float m = -INFINITY, s = 0.f;

    struct EdgeC { uint2 k[F4]; uint2 v[F4]; };
    auto loadE = [&](EdgeC& E, int e, bool valid) {
        if (valid) {
            const int src = csr_src[e];
            const uint2* krow = reinterpret_cast<const uint2*>(k + (size_t)src * HC + warp * C);
            const uint2* vrow = reinterpret_cast<const uint2*>(v + (size_t)src * HC + warp * C);
#pragma unroll
            for (int i = 0; i < F4; i++) { E.k[i] = krow[lane + 32 * i]; E.v[i] = vrow[lane + 32 * i]; }
        } else {
#pragma unroll
            for (int i = 0; i < F4; i++) { E.k[i] = make_uint2(0, 0); E.v[i] = make_uint2(0, 0); }
        }
    };
    auto dotk = [&](const EdgeC& E) {
        float d = 0.f;
#pragma unroll
        for (int i = 0; i < F4; i++) {
            const float2 k0 = __half22float2(*reinterpret_cast<const __half2*>(&E.k[i].x));
            const float2 k1 = __half22float2(*reinterpret_cast<const __half2*>(&E.k[i].y));
            d += qr[i].x * k0.x + qr[i].y * k0.y + qr[i].z * k1.x + qr[i].w * k1.y;
        }
        return d;
    };

    EdgeC c0, c1, n0, n1;
    if (beg < end) {
        loadE(c0, beg, true);
        loadE(c1, beg + 1, beg + 1 < end);
    }

    for (int j = beg; j < end; j += 2) {
        if (j + 2 < end) {
            loadE(n0, j + 2, true);
            loadE(n1, j + 3, j + 3 < end);
        }
        float d1 = dotk(c0);
        float d2 = dotk(c1);
#pragma unroll
        for (int o = 16; o > 0; o >>= 1) {
            d1 += __shfl_xor_sync(0xffffffffu, d1, o);
            d2 += __shfl_xor_sync(0xffffffffu, d2, o);
        }
        const float a1 = d1 * scale;
        const float a2 = (j + 1 < end) ? d2 * scale : -INFINITY;
        const float mn = fmaxf(m, fmaxf(a1, a2));
        const float corr = expf(m - mn);
        const float w1 = expf(a1 - mn);
        const float w2 = expf(a2 - mn);
        s = s * corr + w1 + w2;
        m = mn;
#pragma unroll
        for (int i = 0; i < F4; i++) {
            const float2 u0 = __half22float2(*reinterpret_cast<const __half2*>(&c0.v[i].x));
            const float2 u1 = __half22float2(*reinterpret_cast<const __half2*>(&c0.v[i].y));
            const float2 w0 = __half22float2(*reinterpret_cast<const __half2*>(&c1.v[i].x));
            const float2 w1v = __half22float2(*reinterpret_cast<const __half2*>(&c1.v[i].y));
            acc[i].x = acc[i].x * corr + w1 * u0.x + w2 * w0.x;
            acc[i].y = acc[i].y * corr + w1 * u0.y + w2 * w0.y;
            acc[i].z = acc[i].z * corr + w1 * u1.x + w2 * w1v.x;
            acc[i].w = acc[i].w * corr + w1 * u1.y + w2 * w1v.y;
        }
        c0 = n0;
        c1 = n1;
    }

    const float inv = (end > beg) ? (1.f / (s + 1e-16f)) : 0.f;
#pragma unroll
    for (int i = 0; i < F4; i++) {
        float4 o = make_float4(acc[i].x * inv, acc[i].y * inv, acc[i].z * inv, acc[i].w * inv);
        *reinterpret_cast<float4*>(&red[warp * C + i * 128 + lane * 4]) = o;
    }
    __syncthreads();

    float part = 0.f;
    for (int f = threadIdx.x; f < C; f += blockDim.x) {
        float t = 0.f;
#pragma unroll
        for (int h = 0; h < H; h++) t += red[h * C + f];
        t = t * (1.f / H) + skip[(size_t)dst * C + f];
        t = (t > 0.f) ? t : expm1f(t);
        const size_t idx = (size_t)dst * C + f;
        if constexpr (F16OUT) {
            outF16[idx] = __float2half(t);
        } else {
            out[idx] = t;
            part += t * wg[f];
        }
    }

    if constexpr (!F16OUT) {
        __syncthreads();
        red[threadIdx.x] = part;
        __syncthreads();
#pragma unroll
        for (int off = 128; off > 0; off >>= 1) {
            if (threadIdx.x < off) red[threadIdx.x] += red[threadIdx.x + off];
            __syncthreads();
        }
        if (threadIdx.x == 0) {
            const float d = red[0] + bg[0];
            gate[dst] = d;
            float* addr = &gmax[batch[dst]];
            if (d >= 0.f) atomicMax((int*)addr, __float_as_int(d));
            else          atomicMin((unsigned int*)addr, __float_as_uint(d));
        }
    }
}

// ---------------- pooling + fc ----------------
__global__ void exp_pool(const float* __restrict__ h, const float* __restrict__ gate,
                         const int* __restrict__ batch, const float* __restrict__ gmax,
                         float* __restrict__ gsum, float* __restrict__ pool)
{
    const int node = blockIdx.x;
    const int f = threadIdx.x;
    const int b = batch[node];
    const float e = expf(gate[node] - gmax[b]);
    if (f == 0) atomicAdd(&gsum[b], e);
    atomicAdd(&pool[b * D3 + f], e * h[(size_t)node * D3 + f]);
}

__global__ void fc_kernel(const float* __restrict__ pool, const float* __restrict__ gsum,
                          const float* __restrict__ wfc, const float* __restrict__ bfc,
                          float* __restrict__ out)
{
    const int t = threadIdx.x;
    if (t >= N_GRAPHS * OUT_DIM) return;
    const int g = t / OUT_DIM, o = t % OUT_DIM;
    float s = 0.f;
#pragma unroll 16
    for (int f = 0; f < D3; f++) s += pool[g * D3 + f] * wfc[f * OUT_DIM + o];
    out[g * OUT_DIM + o] = s / (gsum[g] + 1e-16f) + bfc[o];
}

// ---------------- launch ----------------
extern "C" void kernel_launch(void* const* d_in, const int* in_sizes, int n_in,
                              void* d_out, int out_size)
{
    const float* x     = (const float*)d_in[0];
    const int*   ei    = (const int*)d_in[1];
    const int*   batch = (const int*)d_in[2];
    const float* W[12] = { (const float*)d_in[3],  (const float*)d_in[5],
                           (const float*)d_in[7],  (const float*)d_in[9],
                           (const float*)d_in[11], (const float*)d_in[13],
                           (const float*)d_in[15], (const float*)d_in[17],
                           (const float*)d_in[19], (const float*)d_in[21],
                           (const float*)d_in[23], (const float*)d_in[25] };
    const float* Bv[12] = { (const float*)d_in[4],  (const float*)d_in[6],
                            (const float*)d_in[8],  (const float*)d_in[10],
                            (const float*)d_in[12], (const float*)d_in[14],
                            (const float*)d_in[16], (const float*)d_in[18],
                            (const float*)d_in[20], (const float*)d_in[22],
                            (const float*)d_in[24], (const float*)d_in[26] };
    const float* w_g  = (const float*)d_in[27]; const float* b_g  = (const float*)d_in[28];
    const float* w_fc = (const float*)d_in[29]; const float* b_fc = (const float*)d_in[30];
    float* out = (float*)d_out;

    float *qb, *skipb, *hA, *gateb, *gmaxb, *gsumb, *poolb, *biasb, *extrasb;
    __half *kb, *vb, *x16b, *Af16b, *WFb, *A16b, *BT16b;
    int *degb, *ptrb, *fillb, *csrb;
    cudaGetSymbolAddress((void**)&qb,     g_q);
    cudaGetSymbolAddress((void**)&kb,     g_k);
    cudaGetSymbolAddress((void**)&vb,     g_v);
    cudaGetSymbolAddress((void**)&skipb,  g_skip);
    cudaGetSymbolAddress((void**)&hA,     g_hA);
    cudaGetSymbolAddress((void**)&extrasb,g_extras);
    cudaGetSymbolAddress((void**)&x16b,   g_x16);
    cudaGetSymbolAddress((void**)&Af16b,  g_Af16);
    cudaGetSymbolAddress((void**)&A16b,   g_A16);
    cudaGetSymbolAddress((void**)&BT16b,  g_BT16);
    cudaGetSymbolAddress((void**)&WFb,    g_WF);
    cudaGetSymbolAddress((void**)&biasb,  g_bias);
    cudaGetSymbolAddress((void**)&degb,   g_deg);
    cudaGetSymbolAddress((void**)&ptrb,   g_ptr);
    cudaGetSymbolAddress((void**)&fillb,  g_fill);
    cudaGetSymbolAddress((void**)&csrb,   g_csr_src);
    cudaGetSymbolAddress((void**)&gateb,  g_gate);
    cudaGetSymbolAddress((void**)&gmaxb,  g_gmax);
    cudaGetSymbolAddress((void**)&gsumb,  g_gsum);
    cudaGetSymbolAddress((void**)&poolb,  g_pool);

    const int N = N_NODES, E = N_EDGES;

    // ---- pack regions ----
    PackArgs P;
    long long wcum = 0;
    int bcum = 0;
    int ri = 0;
    auto addW = [&](const float* src, int K, int ncols, long long base, int ntot, int coff,
                    const float* bsrc, int boff) {
        P.wsrc[ri] = src; P.wcum[ri] = wcum; P.wncols[ri] = ncols;
        P.wdstBase[ri] = base; P.wntot[ri] = ntot; P.wcoff[ri] = coff;
        wcum += (long long)K * ncols;
        P.bsrc[ri] = bsrc; P.bcum[ri] = bcum; P.boff[ri] = boff;
        bcum += ncols;
        ri++;
    };
    addW(W[2], F_IN, HEADS * D1, WF_BASE1, F_N1, MCOLS, Bv[2], BB1 + MCOLS);
    addW(W[3], F_IN, D1, WF_BASE1, F_N1, MCOLS + HEADS * D1, Bv[3], BB1 + MCOLS + HEADS * D1);
    for (int p = 0; p < 4; p++) {
        const int ncols = (p < 3) ? HEADS * D2 : D2;
        const int coff = (p < 3) ? p * HEADS * D2 : 3 * HEADS * D2;
        addW(W[4 + p], D1, ncols, WF_BASE2, F_N2, coff, Bv[4 + p], BB2 + coff);
    }
    for (int p = 0; p < 4; p++) {
        const int ncols = (p < 3) ? HEADS * D3 : D3;
        const int coff = (p < 3) ? p * HEADS * D3 : 3 * HEADS * D3;
        addW(W[8 + p], D2, ncols, WF_BASE3, F_N3, coff, Bv[8 + p], BB3 + coff);
    }
    P.wcum[ri] = wcum;
    P.bcum[ri] = bcum;
    for (int r2 = ri; r2 < 12; r2++) { P.wcum[r2 + 1] = wcum; P.bcum[r2 + 1] = bcum; }
    P.x = x;
    P.wq = W[0];
    P.wk = W[1];
    P.bq = Bv[0];
    P.bk = Bv[1];
    P.ei = ei;

    const long long packTotal = wcum + NXTOT + bcum + QKTOT + E + POOLINIT + EXTOT;
    const int gy = (N + 127) / 128;

    // epilogue tables
    EpiTab T1;
    T1.start[0] = 0;     T1.f[0] = qb;      T1.h[0] = nullptr; T1.stride[0] = ZCOLS;
    T1.start[1] = ZCOLS; T1.f[1] = extrasb; T1.h[1] = nullptr; T1.stride[1] = 128;
    T1.start[2] = MCOLS; T1.f[2] = nullptr; T1.h[2] = vb;      T1.stride[2] = HEADS * D1;
    T1.start[3] = MCOLS + HEADS * D1; T1.f[3] = skipb; T1.h[3] = nullptr; T1.stride[3] = D1;
    EpiTab T2;
    T2.start[0] = 0;              T2.f[0] = qb;      T2.h[0] = nullptr; T2.stride[0] = HEADS * D2;
    T2.start[1] = HEADS * D2;     T2.f[1] = nullptr; T2.h[1] = kb;      T2.stride[1] = HEADS * D2;
    T2.start[2] = 2 * HEADS * D2; T2.f[2] = nullptr; T2.h[2] = vb;      T2.stride[2] = HEADS * D2;
    T2.start[3] = 3 * HEADS * D2; T2.f[3] = skipb;   T2.h[3] = nullptr; T2.stride[3] = D2;
    EpiTab T3;
    T3.start[0] = 0;              T3.f[0] = qb;      T3.h[0] = nullptr; T3.stride[0] = HEADS * D3;
    T3.start[1] = HEADS * D3;     T3.f[1] = nullptr; T3.h[1] = kb;      T3.stride[1] = HEADS * D3;
    T3.start[2] = 2 * HEADS * D3; T3.f[2] = nullptr; T3.h[2] = vb;      T3.stride[2] = HEADS * D3;
    T3.start[3] = 3 * HEADS * D3; T3.f[3] = skipb;   T3.h[3] = nullptr; T3.stride[3] = D3;

    // launch order: gemm_half L1 at slot 5 (ncu capture)
    cudaMemsetAsync(degb, 0, N * sizeof(int));                                          // 1
    pack_all<<<(int)((packTotal + 255) / 256), 256>>>(P, WFb, x16b, biasb, A16b, BT16b,
                                                      degb, gmaxb, gsumb, poolb,
                                                      wcum, NXTOT, bcum);               // 2
    make_m_mm<<<dim3(1, 8), 256>>>(A16b, BT16b, WFb);                                   // 3
    scan_deg<<<1, 1024>>>(degb, ptrb, fillb, N);                                        // 4
    gemm_half<<<dim3(F_N1 / 128, gy), 256>>>(x16b, WFb + WF_BASE1,
                                             biasb + BB1, T1, N, F_N1, F_IN);           // 5 <- profiled
    fill_csr<<<(E + 255) / 256, 256>>>(ei, fillb, csrb, E);                             // 6
    attn1_kernel<<<N, 256>>>(qb, x16b, extrasb, vb, ptrb, csrb, skipb, Af16b);          // 7

    gemm_half<<<dim3(F_N2 / 128, gy), 256>>>(Af16b, WFb + WF_BASE2,
                                             biasb + BB2, T2, N, F_N2, D1);
    attn_kernel<D2, true><<<N, 256>>>(qb, kb, vb, ptrb, csrb, skipb, nullptr, Af16b,
                                      nullptr, nullptr, nullptr, nullptr, nullptr);

    gemm_half<<<dim3(F_N3 / 128, gy), 256>>>(Af16b, WFb + WF_BASE3,
                                             biasb + BB3, T3, N, F_N3, D2);
    attn_kernel<D3, false><<<N, 256>>>(qb, kb, vb, ptrb, csrb, skipb, hA, nullptr,
                                       w_g, b_g, batch, gateb, gmaxb);

    exp_pool<<<N, D3>>>(hA, gateb, batch, gmaxb, gsumb, poolb);
    fc_kernel<<<1, 1024>>>(poolb, gsumb, w_fc, b_fc, out);
}